// round 11
// baseline (speedup 1.0000x reference)
#include <cuda_runtime.h>
#include <cstdint>

// LSTM seq2seq: encoder (1->64), decoder (1->65, teacher forcing), T=1000,
// B=2048, Linear(65->1) output.
//
// Fused-quad SIMT design: thread t = (quad j = t>>2, slice s = t&3).
// Quad owns the gate quadruple {i,f,g,o} of hidden unit j; each thread holds
// 4 weight rows x 16 cols (64 regs). Per batch row: 4 conflict-free LDS.128
// -> 32 FFMA2 -> 3-shfl combine (thread s ends with one finished gate) ->
// activation -> 3-shfl gather to s0 -> s0 updates c (registers) and writes
// h to the next buffer. h double-buffered => ONE barrier per step, no gates
// smem array. Decoder j=64 quadruple {64,129,194,259} is warp-cooperative;
// output projection overlaps the next step's gate phase.

#define T_STEPS  1000
#define BATCH    2048
#define NCTA     296
#define NTHREADS 256
#define BT_MAX   7
#define HP       84    // h row pitch: cols[16s..16s+15] at s*20, col64 at 80

typedef unsigned long long u64;

struct __align__(16) Smem {
    float h[2][BT_MAX * HP];
    float xbuf[2][8];
};

__device__ __forceinline__ u64 pack2(float lo, float hi) {
    u64 r;
    asm("mov.b64 %0, {%1, %2};" : "=l"(r) : "f"(lo), "f"(hi));
    return r;
}
__device__ __forceinline__ float2 unpack2(u64 v) {
    float lo, hi;
    asm("mov.b64 {%0, %1}, %2;" : "=f"(lo), "=f"(hi) : "l"(v));
    return make_float2(lo, hi);
}
__device__ __forceinline__ void ffma2(u64& d, u64 a, u64 b, u64 c) {
    asm("fma.rn.f32x2 %0, %1, %2, %3;" : "=l"(d) : "l"(a), "l"(b), "l"(c));
}
__device__ __forceinline__ float sigf(float x) {
    return __fdividef(1.0f, 1.0f + __expf(-x));
}
// tanh(x) = 2*sigmoid(2x) - 1
__device__ __forceinline__ float tanh_s(float x) {
    return fmaf(2.0f, sigf(x + x), -1.0f);
}

template <int H, bool DEC, int BTN>
__device__ void lstm_scan(
    Smem& sm, int b0,
    const float* __restrict__ xg,
    const float* __restrict__ Wih,  const float* __restrict__ Whh,
    const float* __restrict__ bih,  const float* __restrict__ bhh,
    float* c, float& c64,
    const float* __restrict__ linW, float linb, float* __restrict__ out)
{
    const int tid  = threadIdx.x;
    const int wid  = tid >> 5;
    const int lane = tid & 31;
    const int s    = tid & 3;
    const int j    = tid >> 2;
    // combine result: s0->gate0(i), s1->gate2(g), s2->gate1(f), s3->gate3(o)
    const int  gidx = (s == 0) ? 0 : (s == 1) ? 2 : (s == 2) ? 1 : 3;
    const int  rowS = gidx * H + j;
    const bool isg  = (s == 1);

    // weight tile: rows {j, H+j, 2H+j, 3H+j} x cols [16s, 16s+16)
    u64 w2[32];
#pragma unroll
    for (int r = 0; r < 4; r++) {
        const float* wr = Whh + (r * H + j) * H + s * 16;
#pragma unroll
        for (int p = 0; p < 8; p++)
            w2[r * 8 + p] = pack2(wr[2 * p], wr[2 * p + 1]);
    }
    const float bias = bih[rowS] + bhh[rowS];
    const float wih  = Wih[rowS];
    const float w64  = DEC ? Whh[rowS * H + 64] : 0.0f;
    const int   hoj  = (j >> 4) * 20 + (j & 15);

    // decoder: j=64 quadruple (warp-cooperative) + projection weights
    float jw[8];
    float jw64 = 0.f, jbias = 0.f, jwih = 0.f;
    float lw0 = 0.f, lw1 = 0.f, lw64v = 0.f;
    if constexpr (DEC) {
        const int r     = lane >> 3;            // gate row (i,f,g,o)
        const int row64 = r * H + 64;
        const int cb    = (lane & 7) * 8;       // 8 cols per lane
#pragma unroll
        for (int cc = 0; cc < 8; cc++)
            jw[cc] = Whh[row64 * H + cb + cc];
        if ((lane & 7) == 0) {
            jw64  = Whh[row64 * H + 64];
            jbias = bih[row64] + bhh[row64];
            jwih  = Wih[row64];
        }
        lw0 = linW[lane]; lw1 = linW[lane + 32]; lw64v = linW[64];
    }

    int cur = 0;
    for (int t = 0; t < T_STEPS; t++) {
        float* hc = sm.h[cur];
        float* hn = sm.h[cur ^ 1];
        const float* xs = sm.xbuf[cur];

        // ---- decoder: projection of step t-1 (hc stable during gate phase) ----
        if constexpr (DEC) {
            if (t > 0 && wid < BTN) {
                const float* hr = hc + wid * HP;
                float p = lw0 * hr[(lane >> 4) * 20 + (lane & 15)]
                        + lw1 * hr[(2 + (lane >> 4)) * 20 + (lane & 15)];
#pragma unroll
                for (int off = 16; off; off >>= 1)
                    p += __shfl_down_sync(0xffffffffu, p, off);
                if (lane == 0)
                    out[(t - 1) * BATCH + b0 + wid] = p + lw64v * hr[80] + linb;
            }
        }

        float xn = 0.f;
        const bool pf = (tid < BTN) && (t + 1 < T_STEPS);
        if (pf) xn = xg[(DEC ? t : t + 1) * BATCH + b0 + tid];

        // ---- fused gate + update, per batch row ----
#pragma unroll 2
        for (int b = 0; b < BTN; b++) {
            const ulonglong2* hp = (const ulonglong2*)(hc + b * HP + s * 20);
            u64 a0 = 0ull, a1 = 0ull, a2 = 0ull, a3 = 0ull;
#pragma unroll
            for (int k = 0; k < 4; k++) {
                ulonglong2 h2 = hp[k];    // 4 disjoint-bank broadcast groups
                ffma2(a0, w2[2 * k],      h2.x, a0); ffma2(a0, w2[2 * k + 1],  h2.y, a0);
                ffma2(a1, w2[8 + 2 * k],  h2.x, a1); ffma2(a1, w2[9 + 2 * k],  h2.y, a1);
                ffma2(a2, w2[16 + 2 * k], h2.x, a2); ffma2(a2, w2[17 + 2 * k], h2.y, a2);
                ffma2(a3, w2[24 + 2 * k], h2.x, a3); ffma2(a3, w2[25 + 2 * k], h2.y, a3);
            }
            float2 v0 = unpack2(a0), v1 = unpack2(a1), v2 = unpack2(a2), v3 = unpack2(a3);
            float p0 = v0.x + v0.y, p1 = v1.x + v1.y, p2 = v2.x + v2.y, p3 = v3.x + v3.y;
            // 3-shfl combine across the 4 col-slices
            float sendA = (s & 1) ? p0 : p2;
            float recvA = __shfl_xor_sync(0xffffffffu, sendA, 1);
            float sendB = (s & 1) ? p1 : p3;
            float recvB = __shfl_xor_sync(0xffffffffu, sendB, 1);
            float aa = ((s & 1) ? p2 : p0) + recvA;
            float bb = ((s & 1) ? p3 : p1) + recvB;
            float sendC = (s & 2) ? aa : bb;
            float recvC = __shfl_xor_sync(0xffffffffu, sendC, 2);
            float fin = ((s & 2) ? bb : aa) + recvC;
            fin += bias + wih * xs[b];
            if constexpr (DEC) fin = fmaf(w64, hc[b * HP + 80], fin);
            // activation (tanh for the g-gate thread, sigmoid otherwise)
            float y = isg ? fin + fin : fin;
            float a = sigf(y);
            if (isg) a = fmaf(2.0f, a, -1.0f);
            // gather activations to s0: g from s1, f from s2, o from s3
            float ag = __shfl_xor_sync(0xffffffffu, a, 1);
            float af = __shfl_xor_sync(0xffffffffu, a, 2);
            float ao = __shfl_xor_sync(0xffffffffu, a, 3);
            if (s == 0) {
                float cn = af * c[b] + a * ag;
                c[b] = cn;
                hn[b * HP + hoj] = ao * tanh_s(cn);
            }
        }

        // ---- decoder: hidden unit 64 (rows {64,129,194,259}), warp w = batch ----
        if constexpr (DEC) {
            if (wid < BTN) {
                const int b = wid;
                const float* hr = hc + b * HP;
                const int cb = (lane & 7) * 8;
                const int o0 = (cb >> 4) * 20 + (cb & 15);
                float p = 0.f;
#pragma unroll
                for (int cc = 0; cc < 8; cc++)
                    p = fmaf(jw[cc], hr[o0 + cc], p);
                if ((lane & 7) == 0) p = fmaf(jw64, hr[80], p);
                p += __shfl_xor_sync(0xffffffffu, p, 4);
                p += __shfl_xor_sync(0xffffffffu, p, 2);
                p += __shfl_xor_sync(0xffffffffu, p, 1);
                float av = 0.f;
                if ((lane & 7) == 0) {
                    const int r = lane >> 3;
                    float g2 = p + jbias + jwih * xs[b];
                    float y2 = (r == 2) ? g2 + g2 : g2;
                    av = sigf(y2);
                    if (r == 2) av = fmaf(2.0f, av, -1.0f);
                }
                float af2 = __shfl_sync(0xffffffffu, av, 8);
                float ag2 = __shfl_sync(0xffffffffu, av, 16);
                float ao2 = __shfl_sync(0xffffffffu, av, 24);
                if (lane == 0) {
                    float cn = af2 * c64 + av * ag2;
                    c64 = cn;
                    hn[b * HP + 80] = ao2 * tanh_s(cn);
                }
            }
        }

        if (pf) sm.xbuf[cur ^ 1][tid] = xn;
        __syncthreads();
        cur ^= 1;
    }

    // ---- decoder: final projection (t = T-1) ----
    if constexpr (DEC) {
        if (wid < BTN) {
            const float* hr = sm.h[cur] + wid * HP;
            float p = lw0 * hr[(lane >> 4) * 20 + (lane & 15)]
                    + lw1 * hr[(2 + (lane >> 4)) * 20 + (lane & 15)];
#pragma unroll
            for (int off = 16; off; off >>= 1)
                p += __shfl_down_sync(0xffffffffu, p, off);
            if (lane == 0)
                out[(T_STEPS - 1) * BATCH + b0 + wid] = p + lw64v * hr[80] + linb;
        }
    }
}

template <int BTN>
__device__ void body(
    Smem& sm, int b0,
    const float* input, const float* speed, const float* target,
    const float* eWih, const float* eWhh, const float* ebih, const float* ebhh,
    const float* dWih, const float* dWhh, const float* dbih, const float* dbhh,
    const float* linW, const float* linb, const float* denseW, const float* denseb,
    float* out)
{
    const int tid = threadIdx.x, wid = tid >> 5, lane = tid & 31;

    for (int i = tid; i < 2 * BT_MAX * HP; i += NTHREADS)
        ((float*)sm.h)[i] = 0.0f;
    if (tid < BTN) sm.xbuf[0][tid] = input[b0 + tid];
    __syncthreads();

    float c[BTN];
#pragma unroll
    for (int b = 0; b < BTN; b++) c[b] = 0.0f;
    float c64 = 0.0f;

    // encoder (H=64). 1000 steps (even) => final h in buffer 0.
    lstm_scan<64, false, BTN>(sm, b0, input, eWih, eWhh, ebih, ebhh,
                              c, c64, nullptr, 0.0f, nullptr);

    // transition: append Dense(speed) as hidden/cell unit 64; x_dec[0] = 0
    if (tid < BTN) {
        float sp = denseb[0] + denseW[0] * speed[b0 + tid];
        sm.h[0][tid * HP + 80] = sp;
        sm.xbuf[0][tid] = 0.0f;
    }
    if (lane == 0 && wid < BTN)
        c64 = denseb[0] + denseW[0] * speed[b0 + wid];
    __syncthreads();

    // decoder (H=65) + projection
    lstm_scan<65, true, BTN>(sm, b0, target, dWih, dWhh, dbih, dbhh,
                             c, c64, linW, linb[0], out);
}

__global__ void __launch_bounds__(NTHREADS, 2)
lstm_seq2seq_kernel(
    const float* __restrict__ input,  const float* __restrict__ speed,
    const float* __restrict__ target,
    const float* __restrict__ eWih,   const float* __restrict__ eWhh,
    const float* __restrict__ ebih,   const float* __restrict__ ebhh,
    const float* __restrict__ dWih,   const float* __restrict__ dWhh,
    const float* __restrict__ dbih,   const float* __restrict__ dbhh,
    const float* __restrict__ linW,   const float* __restrict__ linb,
    const float* __restrict__ denseW, const float* __restrict__ denseb,
    float* __restrict__ out)
{
    __shared__ Smem sm;
    const int cta  = blockIdx.x;
    const int base = BATCH / NCTA;     // 6
    const int rem  = BATCH % NCTA;     // 272
    const int bt   = base + (cta < rem ? 1 : 0);
    const int b0   = cta * base + min(cta, rem);

    if (bt == 7)
        body<7>(sm, b0, input, speed, target, eWih, eWhh, ebih, ebhh,
                dWih, dWhh, dbih, dbhh, linW, linb, denseW, denseb, out);
    else
        body<6>(sm, b0, input, speed, target, eWih, eWhh, ebih, ebhh,
                dWih, dWhh, dbih, dbhh, linW, linb, denseW, denseb, out);
}

extern "C" void kernel_launch(void* const* d_in, const int* in_sizes, int n_in,
                              void* d_out, int out_size)
{
    const float* input  = (const float*)d_in[0];
    const float* speed  = (const float*)d_in[1];
    const float* target = (const float*)d_in[2];
    const float* eWih   = (const float*)d_in[3];
    const float* eWhh   = (const float*)d_in[4];
    const float* ebih   = (const float*)d_in[5];
    const float* ebhh   = (const float*)d_in[6];
    const float* dWih   = (const float*)d_in[7];
    const float* dWhh   = (const float*)d_in[8];
    const float* dbih   = (const float*)d_in[9];
    const float* dbhh   = (const float*)d_in[10];
    const float* linW   = (const float*)d_in[11];
    const float* linb   = (const float*)d_in[12];
    const float* denseW = (const float*)d_in[13];
    const float* denseb = (const float*)d_in[14];
    float* out = (float*)d_out;

    lstm_seq2seq_kernel<<<NCTA, NTHREADS>>>(
        input, speed, target,
        eWih, eWhh, ebih, ebhh,
        dWih, dWhh, dbih, dbhh,
        linW, linb, denseW, denseb, out);
}

// round 12
// speedup vs baseline: 1.3229x; 1.3229x over previous
#include <cuda_runtime.h>

// LSTM seq2seq: encoder (1->64) over T=1000, decoder (1->65) with teacher
// forcing over T=1000, output Linear(65->1). B=2048.
//
// Round 12 = round 4 (best: 256 thr, 2 CTA/SM, thread=(pair,half) owns
// 2 gate rows x 32-col k-half, 1-shfl combine, gates in smem) plus:
//  - c in registers across each scan (smem only at enc->dec transition)
//  - gates stored interleaved+swizzled: row g=(gate,j) at 4j+((gate+(j>>3))&3)
//    -> STS conflict-free AND update reads its 4 gates as ONE LDS.128
//    (+2-level rotate-select), instead of 4 scattered LDS
//  - decoder loop-invariant weights hoisted out of the 1000-step loop
//  - tanh(x) = 2*sigmoid(2x)-1 (branchless)

#define T_STEPS   1000
#define BATCH     2048
#define NCTA      296
#define NTHREADS  256
#define NWARPS    (NTHREADS / 32)
#define BT_MAX    7
#define HP        72     // h row pitch; cols0-31 at +0, cols32-63 at +36, col64 at +68
#define GP        264    // gates row pitch (66 float4 slots; unit j at float4 slot j)

typedef unsigned long long u64;

struct Smem {
    float h[BT_MAX * HP];   // split layout
    float c[BT_MAX * HP];   // linear; init + enc->dec transition only
    float gates[BT_MAX * GP];
    float xbuf[2][BT_MAX];
    float xw[4 * 68];       // decoder gate rows 256..259 (65 weights, linear)
    float xwih[4];
    float xbias[4];
    float linW[68];
};

__device__ __forceinline__ u64 pack2(float lo, float hi) {
    u64 r;
    asm("mov.b64 %0, {%1, %2};" : "=l"(r) : "f"(lo), "f"(hi));
    return r;
}
__device__ __forceinline__ float2 unpack2(u64 v) {
    float lo, hi;
    asm("mov.b64 {%0, %1}, %2;" : "=f"(lo), "=f"(hi) : "l"(v));
    return make_float2(lo, hi);
}
__device__ __forceinline__ void ffma2(u64& d, u64 a, u64 b, u64 c) {
    asm("fma.rn.f32x2 %0, %1, %2, %3;" : "=l"(d) : "l"(a), "l"(b), "l"(c));
}
__device__ __forceinline__ float sigf(float x) {
    return __fdividef(1.0f, 1.0f + __expf(-x));
}
__device__ __forceinline__ float tanh_s(float x) {
    return fmaf(2.0f, sigf(x + x), -1.0f);
}

// swizzled gate slot for row (gate, j): float index 4j + ((gate + (j>>3)) & 3)
__device__ __forceinline__ int gate_off(int gate, int j) {
    return 4 * j + ((gate + ((j >> 3) & 3)) & 3);
}

template <int H, int NB>
__device__ __forceinline__ void gate_block(
    Smem& sm, const float* xs, int b,
    const u64* w2, float wrem0, float wrem1,
    float wih_g, float bias_g, int goff, int half)
{
    u64 a0[NB], a1[NB];
    const ulonglong2* hp[NB];
#pragma unroll
    for (int u = 0; u < NB; u++) {
        a0[u] = 0ull;
        a1[u] = 0ull;
        hp[u] = (const ulonglong2*)(sm.h + (b + u) * HP + half * 36);
    }
#pragma unroll
    for (int q = 0; q < 8; q++) {
#pragma unroll
        for (int u = 0; u < NB; u++) {
            ulonglong2 h2 = hp[u][q];   // 2 disjoint-bank broadcast groups
            ffma2(a0[u], w2[2 * q],      h2.x, a0[u]);
            ffma2(a0[u], w2[2 * q + 1],  h2.y, a0[u]);
            ffma2(a1[u], w2[16 + 2 * q], h2.x, a1[u]);
            ffma2(a1[u], w2[17 + 2 * q], h2.y, a1[u]);
        }
    }
#pragma unroll
    for (int u = 0; u < NB; u++) {
        float2 s0 = unpack2(a0[u]);
        float2 s1 = unpack2(a1[u]);
        float p0 = s0.x + s0.y;
        float p1 = s1.x + s1.y;
        if constexpr (H == 65) {
            const float h64 = sm.h[(b + u) * HP + 68];
            p0 = fmaf(wrem0, h64, p0);
            p1 = fmaf(wrem1, h64, p1);
        }
        const float send = half ? p0 : p1;
        const float recv = __shfl_xor_sync(0xffffffffu, send, 1);
        const float own  = half ? p1 : p0;
        sm.gates[(b + u) * GP + goff] = fmaf(wih_g, xs[b + u], bias_g + own + recv);
    }
}

template <int H, bool IS_DEC>
__device__ void lstm_scan(
    Smem& sm, int bt, int b0,
    const float* __restrict__ xglob,
    const float* __restrict__ Wih,
    const float* __restrict__ Whh,
    const float* __restrict__ bih,
    const float* __restrict__ bhh,
    float* __restrict__ out,
    float linb)
{
    const int tid  = threadIdx.x;
    const int wid  = tid >> 5;
    const int lane = tid & 31;
    const int pair = tid >> 1;
    const int half = tid & 1;

    // ---- weight tile: rows {2p, 2p+1}, cols [32*half, 32*half+32) ----
    u64   w2[32];
    float wrem0 = 0.0f, wrem1 = 0.0f;
    float wih_g, bias_g;
    {
        const int r0 = 2 * pair, r1 = r0 + 1;
        const float* wr0 = Whh + r0 * H + half * 32;
        const float* wr1 = Whh + r1 * H + half * 32;
#pragma unroll
        for (int p = 0; p < 16; p++) {
            w2[p]      = pack2(wr0[2 * p], wr0[2 * p + 1]);
            w2[16 + p] = pack2(wr1[2 * p], wr1[2 * p + 1]);
        }
        if constexpr (H == 65) {
            if (half) {
                wrem0 = Whh[r0 * H + 64];
                wrem1 = Whh[r1 * H + 64];
            }
        }
        wih_g  = Wih[tid];
        bias_g = bih[tid] + bhh[tid];
    }
    // finalized row tid -> (gate, j) -> swizzled gate offset
    int goff;
    {
        const int gate = (H == 64) ? (tid >> 6) : (tid / 65);
        const int j    = (H == 64) ? (tid & 63) : (tid - gate * 65);
        goff = gate_off(gate, j);
    }

    // ---- update mapping (loop-invariant), c in registers ----
    int ucnt = 0;
    int ub[2], ujj[2], uha[2], urot[2];
    float cr[2];
    {
        const int npairs = H * bt;
        for (int p = tid; p < npairs; p += NTHREADS) {
            const int b = p / H;
            const int j = p - b * H;
            ub[ucnt]   = b;
            ujj[ucnt]  = j;
            uha[ucnt]  = b * HP + ((j < 32) ? j : (j < 64) ? (j + 4) : 68);
            urot[ucnt] = (j >> 3) & 3;
            cr[ucnt]   = sm.c[b * HP + j];
            ucnt++;
        }
    }

    // ---- decoder loop-invariant hoists ----
    float lw0 = 0.f, lw1 = 0.f, lw64 = 0.f;
    int   tcnt = 0;
    int   tb[4], tgo[4], tei[4];
    float twe0[4], twe1[4], twe64[4];
    if constexpr (IS_DEC) {
        lw0  = sm.linW[lane];
        lw1  = sm.linW[lane + 32];
        lw64 = sm.linW[64];
        const int ntask = 4 * bt;
        for (int task = wid; task < ntask && tcnt < 4; task += NWARPS) {
            const int e = task & 3;       // row 256+e = gate 3, unit j = 61+e
            const int j = 61 + e;
            tei[tcnt]   = e;
            tb[tcnt]    = task >> 2;
            tgo[tcnt]   = gate_off(3, j);
            twe0[tcnt]  = sm.xw[e * 68 + lane];
            twe1[tcnt]  = sm.xw[e * 68 + lane + 32];
            twe64[tcnt] = sm.xw[e * 68 + 64];
            tcnt++;
        }
    }

    for (int t = 0; t < T_STEPS; t++) {
        float xnext = 0.0f;
        const bool do_pref = (tid < bt) && (t + 1 < T_STEPS);
        if (do_pref) {
            const int row = IS_DEC ? t : (t + 1);
            xnext = xglob[row * BATCH + b0 + tid];
        }
        const float* xs = sm.xbuf[t & 1];

        // ---- gate phase ----
        {
            int b = 0;
            for (; b + 4 <= bt; b += 4)
                gate_block<H, 4>(sm, xs, b, w2, wrem0, wrem1, wih_g, bias_g, goff, half);
            const int rem = bt - b;
            if (rem == 1)      gate_block<H, 1>(sm, xs, b, w2, wrem0, wrem1, wih_g, bias_g, goff, half);
            else if (rem == 2) gate_block<H, 2>(sm, xs, b, w2, wrem0, wrem1, wih_g, bias_g, goff, half);
            else if (rem == 3) gate_block<H, 3>(sm, xs, b, w2, wrem0, wrem1, wih_g, bias_g, goff, half);
        }

        // ---- decoder: leftover rows 256..259 (gate3, units 61..64) ----
        if constexpr (IS_DEC) {
#pragma unroll
            for (int i = 0; i < 4; i++) {
                if (i < tcnt) {
                    const int b = tb[i];
                    const float* hrow = sm.h + b * HP;
                    float p = twe0[i] * hrow[lane] + twe1[i] * hrow[36 + lane];
                    if (lane == 0) p += twe64[i] * hrow[68];
#pragma unroll
                    for (int off = 16; off; off >>= 1)
                        p += __shfl_down_sync(0xffffffffu, p, off);
                    if (lane == 0)
                        sm.gates[b * GP + tgo[i]] =
                            sm.xbias[tei[i]] + sm.xwih[tei[i]] * xs[b] + p;
                }
            }
        }

        if (do_pref) sm.xbuf[(t + 1) & 1][tid] = xnext;
        __syncthreads();

        // ---- pointwise LSTM update: 1 LDS.128 per element + rotate-select ----
#pragma unroll
        for (int k = 0; k < 2; k++) {
            if (k < ucnt) {
                const float4 g4 = ((const float4*)(sm.gates + ub[k] * GP))[ujj[k]];
                const int rot = urot[k];
                // y[g] = x[(g+rot)&3]; two conditional rotates
                const bool r1 = rot & 1, r2 = rot & 2;
                const float t0 = r1 ? g4.y : g4.x;
                const float t1 = r1 ? g4.z : g4.y;
                const float t2 = r1 ? g4.w : g4.z;
                const float t3 = r1 ? g4.x : g4.w;
                const float gi = r2 ? t2 : t0;
                const float gf = r2 ? t3 : t1;
                const float gg = r2 ? t0 : t2;
                const float go = r2 ? t1 : t3;
                const float cn = sigf(gf) * cr[k] + sigf(gi) * tanh_s(gg);
                cr[k] = cn;
                sm.h[uha[k]] = sigf(go) * tanh_s(cn);
            }
        }
        __syncthreads();

        // ---- decoder: output projection ----
        if constexpr (IS_DEC) {
            for (int b = wid; b < bt; b += NWARPS) {
                const float* hrow = sm.h + b * HP;
                float p = lw0 * hrow[lane] + lw1 * hrow[36 + lane];
                if (lane == 0) p += lw64 * hrow[68];
#pragma unroll
                for (int off = 16; off; off >>= 1)
                    p += __shfl_down_sync(0xffffffffu, p, off);
                if (lane == 0)
                    out[t * BATCH + b0 + b] = p + linb;
            }
        }
    }

    // ---- write c back (needed for the enc->dec transition remap) ----
    if constexpr (!IS_DEC) {
#pragma unroll
        for (int k = 0; k < 2; k++)
            if (k < ucnt) sm.c[ub[k] * HP + ujj[k]] = cr[k];
    }
}

__global__ void __launch_bounds__(NTHREADS, 2)
lstm_seq2seq_kernel(
    const float* __restrict__ input,  const float* __restrict__ speed,
    const float* __restrict__ target,
    const float* __restrict__ eWih,   const float* __restrict__ eWhh,
    const float* __restrict__ ebih,   const float* __restrict__ ebhh,
    const float* __restrict__ dWih,   const float* __restrict__ dWhh,
    const float* __restrict__ dbih,   const float* __restrict__ dbhh,
    const float* __restrict__ linW,   const float* __restrict__ linb,
    const float* __restrict__ denseW, const float* __restrict__ denseb,
    float* __restrict__ out)
{
    __shared__ Smem sm;
    const int tid  = threadIdx.x;
    const int cta  = blockIdx.x;
    const int base = BATCH / NCTA;     // 6
    const int rem  = BATCH % NCTA;     // 272
    const int bt   = base + (cta < rem ? 1 : 0);
    const int b0   = cta * base + min(cta, rem);

    for (int i = tid; i < BT_MAX * HP; i += NTHREADS) {
        sm.h[i] = 0.0f;
        sm.c[i] = 0.0f;
    }
    for (int i = tid; i < 4 * 65; i += NTHREADS) {
        const int e = i / 65, k = i - e * 65;
        sm.xw[e * 68 + k] = dWhh[(256 + e) * 65 + k];
    }
    if (tid < 4) {
        sm.xwih[tid]  = dWih[256 + tid];
        sm.xbias[tid] = dbih[256 + tid] + dbhh[256 + tid];
    }
    for (int i = tid; i < 65; i += NTHREADS) sm.linW[i] = linW[i];
    if (tid < bt) sm.xbuf[0][tid] = input[b0 + tid];
    const float lb = linb[0];
    __syncthreads();

    // ---- encoder scan (H=64) ----
    lstm_scan<64, false>(sm, bt, b0, input, eWih, eWhh, ebih, ebhh, nullptr, 0.0f);
    __syncthreads();

    // ---- transition: append Dense(speed) to hidden & cell, zero dec x0 ----
    if (tid < bt) {
        const float sp = denseb[0] + denseW[0] * speed[b0 + tid];
        sm.h[tid * HP + 68] = sp;      // h split layout: col 64 at +68
        sm.c[tid * HP + 64] = sp;      // c linear
        sm.xbuf[0][tid] = 0.0f;
    }
    __syncthreads();

    // ---- decoder scan (H=65) + output projection ----
    lstm_scan<65, true>(sm, bt, b0, target, dWih, dWhh, dbih, dbhh, out, lb);
}

extern "C" void kernel_launch(void* const* d_in, const int* in_sizes, int n_in,
                              void* d_out, int out_size)
{
    const float* input  = (const float*)d_in[0];
    const float* speed  = (const float*)d_in[1];
    const float* target = (const float*)d_in[2];
    const float* eWih   = (const float*)d_in[3];
    const float* eWhh   = (const float*)d_in[4];
    const float* ebih   = (const float*)d_in[5];
    const float* ebhh   = (const float*)d_in[6];
    const float* dWih   = (const float*)d_in[7];
    const float* dWhh   = (const float*)d_in[8];
    const float* dbih   = (const float*)d_in[9];
    const float* dbhh   = (const float*)d_in[10];
    const float* linW   = (const float*)d_in[11];
    const float* linb   = (const float*)d_in[12];
    const float* denseW = (const float*)d_in[13];
    const float* denseb = (const float*)d_in[14];
    float* out = (float*)d_out;

    lstm_seq2seq_kernel<<<NCTA, NTHREADS>>>(
        input, speed, target,
        eWih, eWhh, ebih, ebhh,
        dWih, dWhh, dbih, dbhh,
        linW, linb, denseW, denseb, out);
}